// round 15
// baseline (speedup 1.0000x reference)
#include <cuda_runtime.h>
#include <cuda_bf16.h>
#include <math.h>
#include <stdint.h>

#define NPTS 6144
#define DIM  64
#define FFD  256
#define EPSf 1e-5f

// ---------------- device scratch (no allocations allowed) ----------------
__device__ uint32_t g_qkh[NPTS*32];     // qk projection, bf16x2 packed [row][kp]
__device__ uint32_t g_vth[64*(NPTS/2)]; // V transposed+packed: [d][kp] word=(V[2kp][d],V[2kp+1][d])
__device__ float g_h1 [NPTS*DIM];
__device__ float g_h2 [NPTS*DIM];
__device__ float g_ffh[NPTS*FFD];
__device__ float g_y  [NPTS*DIM];
__device__ float g_xa [NPTS*3];
__device__ float g_po [3*NPTS*DIM];
__device__ float g_l  [3*NPTS];
__device__ float g_part[96*128];

#define KPTOT (NPTS/2)   // 3072 kp words per d-row of Vt

// =====================================================================
// mma / ldmatrix helpers
// =====================================================================
__device__ __forceinline__ void mma_tf32(float c[4], const uint32_t a[4],
                                         uint32_t b0, uint32_t b1) {
    asm volatile(
        "mma.sync.aligned.m16n8k8.row.col.f32.tf32.tf32.f32 "
        "{%0,%1,%2,%3}, {%4,%5,%6,%7}, {%8,%9}, {%0,%1,%2,%3};"
        : "+f"(c[0]), "+f"(c[1]), "+f"(c[2]), "+f"(c[3])
        : "r"(a[0]), "r"(a[1]), "r"(a[2]), "r"(a[3]), "r"(b0), "r"(b1));
}

__device__ __forceinline__ void mma_bf16(float c[4], const uint32_t a[4],
                                         uint32_t b0, uint32_t b1) {
    asm volatile(
        "mma.sync.aligned.m16n8k16.row.col.f32.bf16.bf16.f32 "
        "{%0,%1,%2,%3}, {%4,%5,%6,%7}, {%8,%9}, {%0,%1,%2,%3};"
        : "+f"(c[0]), "+f"(c[1]), "+f"(c[2]), "+f"(c[3])
        : "r"(a[0]), "r"(a[1]), "r"(a[2]), "r"(a[3]), "r"(b0), "r"(b1));
}

__device__ __forceinline__ void ldsm4(uint32_t d[4], uint32_t saddr) {
    asm volatile("ldmatrix.sync.aligned.m8n8.x4.shared.b16 {%0,%1,%2,%3}, [%4];"
        : "=r"(d[0]), "=r"(d[1]), "=r"(d[2]), "=r"(d[3]) : "r"(saddr));
}

__device__ __forceinline__ void cpa16g(void* sdst, const void* gsrc) {
    uint32_t sa = (uint32_t)__cvta_generic_to_shared(sdst);
    asm volatile("cp.async.cg.shared.global [%0], [%1], 16;" :: "r"(sa), "l"(gsrc));
}

// =====================================================================
// V pack+transpose: Vt[d][kp] = bf16x2(V[2kp][d], V[2kp+1][d])
// smem stride 68 (16B-aligned rows for float4; bank-shifted)
// =====================================================================
__global__ void __launch_bounds__(256) vpack_kernel(
    const float* __restrict__ V, uint32_t* __restrict__ Vt)
{
    __shared__ float sV[64][68];
    int t = threadIdx.x;
    int rbase = blockIdx.x * 64;        // 64 rows = 32 kp
    int kpb   = blockIdx.x * 32;

    #pragma unroll
    for (int it = 0; it < 4; it++) {
        int i = t + it*256, r = i >> 4, d4 = i & 15;
        *(float4*)(&sV[r][d4*4]) = *(const float4*)(V + (rbase+r)*64 + d4*4);
    }
    __syncthreads();

    int d = t >> 2, g = t & 3;
    #pragma unroll
    for (int j = 0; j < 8; j++) {
        int kp = g*8 + j;
        __nv_bfloat162 h = __floats2bfloat162_rn(sV[2*kp][d], sV[2*kp+1][d]);
        Vt[d*KPTOT + kpb + kp] = *(uint32_t*)&h;
    }
}

// =====================================================================
// Tensor-core GEMM (tf32): C = A@W + b ; opt relu; opt BN partials
// =====================================================================
template<int LDW, bool RELU, bool BNP>
__global__ void __launch_bounds__(256) gemm_tc_kernel(
    const float* __restrict__ A, const float* __restrict__ W,
    const float* __restrict__ bias, float* __restrict__ C,
    float* __restrict__ part)
{
    __shared__ float sA[64*68];
    __shared__ float sW[64*72];
    int t = threadIdx.x;
    int lane = t & 31, wid = t >> 5;
    int gid = lane >> 2, l4 = lane & 3;
    int mw = wid & 3, nw = wid >> 2;
    int rbase = blockIdx.x * 64;
    int cb    = blockIdx.y * 64;

    #pragma unroll
    for (int it = 0; it < 4; it++) {
        int i = t + it*256, r = i >> 4, d4 = i & 15;
        *(float4*)(sA + r*68 + d4*4) = *(const float4*)(A + (rbase+r)*64 + d4*4);
        *(float4*)(sW + r*72 + d4*4) = *(const float4*)(W + r*LDW + cb + d4*4);
    }
    __syncthreads();

    float acc[4][4];
    #pragma unroll
    for (int nb = 0; nb < 4; nb++)
        #pragma unroll
        for (int j = 0; j < 4; j++) acc[nb][j] = 0.f;

    int r0 = mw*16 + gid;
    #pragma unroll
    for (int ks = 0; ks < 8; ks++) {
        uint32_t a[4];
        int c0 = ks*8 + l4;
        a[0] = __float_as_uint(sA[ r0    *68 + c0    ]);
        a[1] = __float_as_uint(sA[(r0+8)*68 + c0    ]);
        a[2] = __float_as_uint(sA[ r0    *68 + c0 + 4]);
        a[3] = __float_as_uint(sA[(r0+8)*68 + c0 + 4]);
        #pragma unroll
        for (int nb = 0; nb < 4; nb++) {
            int dcol = nw*32 + nb*8 + gid;
            uint32_t b0 = __float_as_uint(sW[(ks*8 + l4    )*72 + dcol]);
            uint32_t b1 = __float_as_uint(sW[(ks*8 + l4 + 4)*72 + dcol]);
            mma_tf32(acc[nb], a, b0, b1);
        }
    }

    if (BNP) __syncthreads();
    float* sp1 = sW;
    float* sp2 = sW + 2048;

    #pragma unroll
    for (int nb = 0; nb < 4; nb++) {
        int col = cb + nw*32 + nb*8 + l4*2;
        float b0 = __ldg(bias + col), b1 = __ldg(bias + col + 1);
        float v00 = acc[nb][0] + b0, v01 = acc[nb][1] + b1;
        float v10 = acc[nb][2] + b0, v11 = acc[nb][3] + b1;
        if (RELU) {
            v00 = fmaxf(0.f, v00); v01 = fmaxf(0.f, v01);
            v10 = fmaxf(0.f, v10); v11 = fmaxf(0.f, v11);
        }
        *(float2*)(C + (rbase + r0    )*LDW + col) = make_float2(v00, v01);
        *(float2*)(C + (rbase + r0 + 8)*LDW + col) = make_float2(v10, v11);
        if (BNP) {
            int lc = nw*32 + nb*8 + l4*2;
            int slot = (mw*8 + gid)*64;
            sp1[slot + lc    ] = v00 + v10;
            sp1[slot + lc + 1] = v01 + v11;
            sp2[slot + lc    ] = v00*v00 + v10*v10;
            sp2[slot + lc + 1] = v01*v01 + v11*v11;
        }
    }
    if (BNP) {
        __syncthreads();
        if (t < 64) {
            float s1 = 0.f, s2 = 0.f;
            #pragma unroll 8
            for (int k = 0; k < 32; k++) {
                s1 += sp1[k*64 + t];
                s2 += sp2[k*64 + t];
            }
            part[blockIdx.x*128 + t]      = s1;
            part[blockIdx.x*128 + 64 + t] = s2;
        }
    }
}

// =====================================================================
// QK projection GEMM with bf16x2-packed output
// =====================================================================
__global__ void __launch_bounds__(256) gemm_qk_bf16_kernel(
    const float* __restrict__ A, const float* __restrict__ W,
    const float* __restrict__ bias, uint32_t* __restrict__ Ch)
{
    __shared__ float sA[64*68];
    __shared__ float sW[64*72];
    int t = threadIdx.x;
    int lane = t & 31, wid = t >> 5;
    int gid = lane >> 2, l4 = lane & 3;
    int mw = wid & 3, nw = wid >> 2;
    int rbase = blockIdx.x * 64;

    #pragma unroll
    for (int it = 0; it < 4; it++) {
        int i = t + it*256, r = i >> 4, d4 = i & 15;
        *(float4*)(sA + r*68 + d4*4) = *(const float4*)(A + (rbase+r)*64 + d4*4);
        *(float4*)(sW + r*72 + d4*4) = *(const float4*)(W + r*64 + d4*4);
    }
    __syncthreads();

    float acc[4][4];
    #pragma unroll
    for (int nb = 0; nb < 4; nb++)
        #pragma unroll
        for (int j = 0; j < 4; j++) acc[nb][j] = 0.f;

    int r0 = mw*16 + gid;
    #pragma unroll
    for (int ks = 0; ks < 8; ks++) {
        uint32_t a[4];
        int c0 = ks*8 + l4;
        a[0] = __float_as_uint(sA[ r0    *68 + c0    ]);
        a[1] = __float_as_uint(sA[(r0+8)*68 + c0    ]);
        a[2] = __float_as_uint(sA[ r0    *68 + c0 + 4]);
        a[3] = __float_as_uint(sA[(r0+8)*68 + c0 + 4]);
        #pragma unroll
        for (int nb = 0; nb < 4; nb++) {
            int dcol = nw*32 + nb*8 + gid;
            uint32_t b0 = __float_as_uint(sW[(ks*8 + l4    )*72 + dcol]);
            uint32_t b1 = __float_as_uint(sW[(ks*8 + l4 + 4)*72 + dcol]);
            mma_tf32(acc[nb], a, b0, b1);
        }
    }
    #pragma unroll
    for (int nb = 0; nb < 4; nb++) {
        int col = nw*32 + nb*8 + l4*2;
        float b0 = __ldg(bias + col), b1 = __ldg(bias + col + 1);
        __nv_bfloat162 h0 = __floats2bfloat162_rn(acc[nb][0] + b0, acc[nb][1] + b1);
        __nv_bfloat162 h1 = __floats2bfloat162_rn(acc[nb][2] + b0, acc[nb][3] + b1);
        Ch[(rbase + r0    )*32 + (col >> 1)] = *(uint32_t*)&h0;
        Ch[(rbase + r0 + 8)*32 + (col >> 1)] = *(uint32_t*)&h1;
    }
}

// =====================================================================
// Split-K flash v4: FQB=128, registers-only P, ldmatrix B-operands.
// =====================================================================
#define FQB 128
#define FKB 64
#define FSPLIT 3
#define FTILES (NPTS/FKB/FSPLIT)   // 32
#define SKH 36

#define SMEM_FLASH ((2*64*SKH + 2*64*SKH + 128*SKH) * 4)

__global__ void __launch_bounds__(256, 2) flash_tc_kernel(
    const __nv_bfloat16* __restrict__ Qh, const uint32_t* __restrict__ Vt,
    float* __restrict__ PO, float* __restrict__ Lout)
{
    extern __shared__ float sm[];
    uint32_t* sKb = (uint32_t*)sm;               // 2 x 64x36 (keys x kp-words)
    uint32_t* sVb = (uint32_t*)sm + 2*64*SKH;    // 2 x 64x36 (d x kp-words)
    uint32_t* sQ  = (uint32_t*)sm + 4*64*SKH;    // 128x36

    int t = threadIdx.x;
    int lane = t & 31, wid = t >> 5;            // wid = m block (8 x 16 rows)
    int gid = lane >> 2, l4 = lane & 3;
    int m8 = lane >> 3, r8 = lane & 7;          // ldmatrix lane roles
    int qbase = blockIdx.x * FQB;
    int split = blockIdx.y;
    int ktbase = split * FTILES;

    // per-lane ldmatrix byte offsets
    uint32_t boff = (((m8 >> 1)*8 + r8)*SKH + (m8 & 1)*4) * 4;   // B-type (K, Vt)
    uint32_t aoff = (((m8 & 1)*8 + r8)*SKH + (m8 >> 1)*4) * 4;   // A-type (Q)

    // ---- prologue: stage Q (128 rows), K0, V0 ----
    {
        #pragma unroll
        for (int it = 0; it < 4; it++) {
            int idx = t + it*256, r = idx >> 3, c = idx & 7;
            cpa16g(sQ + r*SKH + c*4, Qh + (qbase + r)*64 + c*8);
        }
        #pragma unroll
        for (int it = 0; it < 2; it++) {
            int idx = t + it*256, r = idx >> 3, c = idx & 7;
            cpa16g(sKb + r*SKH + c*4, Qh + (ktbase*FKB + r)*64 + c*8);
        }
        #pragma unroll
        for (int it = 0; it < 2; it++) {
            int idx = t + it*256, d = idx >> 3, c = idx & 7;
            cpa16g(sVb + d*SKH + c*4, Vt + d*KPTOT + ktbase*32 + c*4);
        }
        asm volatile("cp.async.commit_group;");
        asm volatile("cp.async.wait_group 0;");
    }
    __syncthreads();

    // ---- Q fragments via ldmatrix (4 ops) ----
    int r0 = wid*16 + gid;
    uint32_t qa[4][4];
    {
        uint32_t sQl = (uint32_t)__cvta_generic_to_shared(sQ) + wid*16*SKH*4 + aoff;
        #pragma unroll
        for (int ks = 0; ks < 4; ks++)
            ldsm4(qa[ks], sQl + ks*8*4);
    }

    float oc[8][4];
    #pragma unroll
    for (int nb = 0; nb < 8; nb++)
        #pragma unroll
        for (int j = 0; j < 4; j++) oc[nb][j] = 0.f;
    float rs0 = 0.f, rs1 = 0.f;

    uint32_t sK0 = (uint32_t)__cvta_generic_to_shared(sKb);
    uint32_t sV0 = (uint32_t)__cvta_generic_to_shared(sVb);

    for (int kt = 0; kt < FTILES; kt++) {
        int cur = kt & 1;
        uint32_t sKl = sK0 + cur*64*SKH*4 + boff;
        uint32_t sVl = sV0 + cur*64*SKH*4 + boff;

        __syncthreads();
        if (kt + 1 < FTILES) {
            const __nv_bfloat16* Kt = Qh + (ktbase + kt + 1)*FKB*DIM;
            const uint32_t* Vn = Vt + (ktbase + kt + 1)*32;
            uint32_t* dK = sKb + (cur^1)*64*SKH;
            uint32_t* dV = sVb + (cur^1)*64*SKH;
            #pragma unroll
            for (int it = 0; it < 2; it++) {
                int idx = t + it*256, r = idx >> 3, c = idx & 7;
                cpa16g(dK + r*SKH + c*4, Kt + r*64 + c*8);
            }
            #pragma unroll
            for (int it = 0; it < 2; it++) {
                int idx = t + it*256, d = idx >> 3, c = idx & 7;
                cpa16g(dV + d*SKH + c*4, Vn + d*KPTOT + c*4);
            }
            asm volatile("cp.async.commit_group;");
            asm volatile("cp.async.wait_group 1;");
        } else {
            asm volatile("cp.async.wait_group 0;");
        }
        __syncthreads();

        // ---- S = Q @ K^T : 16 ldmatrix + 32 mma ----
        float sc[8][4];
        #pragma unroll
        for (int nb = 0; nb < 8; nb++)
            #pragma unroll
            for (int j = 0; j < 4; j++) sc[nb][j] = 0.f;

        #pragma unroll
        for (int ks = 0; ks < 4; ks++) {
            #pragma unroll
            for (int nbp = 0; nbp < 4; nbp++) {
                uint32_t kb[4];
                ldsm4(kb, sKl + (nbp*16*SKH + ks*8)*4);
                mma_bf16(sc[2*nbp    ], qa[ks], kb[0], kb[1]);
                mma_bf16(sc[2*nbp + 1], qa[ks], kb[2], kb[3]);
            }
        }

        // ---- P = exp(S/8); pack to PV A-fragments in registers ----
        uint32_t pa[4][4];
        #pragma unroll
        for (int nb = 0; nb < 8; nb++) {
            float p0 = __expf(sc[nb][0]*0.125f);
            float p1 = __expf(sc[nb][1]*0.125f);
            float p2 = __expf(sc[nb][2]*0.125f);
            float p3 = __expf(sc[nb][3]*0.125f);
            rs0 += p0 + p1;
            rs1 += p2 + p3;
            __nv_bfloat162 h0 = __floats2bfloat162_rn(p0, p1);
            __nv_bfloat162 h1 = __floats2bfloat162_rn(p2, p3);
            int ks = nb >> 1, hf = (nb & 1)*2;
            pa[ks][hf    ] = *(uint32_t*)&h0;
            pa[ks][hf + 1] = *(uint32_t*)&h1;
        }

        // ---- O += P @ V : 16 ldmatrix + 32 mma ----
        #pragma unroll
        for (int ks = 0; ks < 4; ks++) {
            #pragma unroll
            for (int nbp = 0; nbp < 4; nbp++) {
                uint32_t vb[4];
                ldsm4(vb, sVl + (nbp*16*SKH + ks*8)*4);
                mma_bf16(oc[2*nbp    ], pa[ks], vb[0], vb[1]);
                mma_bf16(oc[2*nbp + 1], pa[ks], vb[2], vb[3]);
            }
        }
    }

    // ---- row sums: reduce over l4 only ----
    rs0 += __shfl_xor_sync(0xffffffffu, rs0, 1);
    rs0 += __shfl_xor_sync(0xffffffffu, rs0, 2);
    rs1 += __shfl_xor_sync(0xffffffffu, rs1, 1);
    rs1 += __shfl_xor_sync(0xffffffffu, rs1, 2);
    if (l4 == 0) {
        Lout[split*NPTS + qbase + r0    ] = rs0;
        Lout[split*NPTS + qbase + r0 + 8] = rs1;
    }
    // ---- epilogue: unnormalized partials ----
    {
        float* po = PO + (split*NPTS + qbase)*DIM;
        #pragma unroll
        for (int nb = 0; nb < 8; nb++) {
            int col = nb*8 + l4*2;
            *(float2*)(po +  r0    *DIM + col) = make_float2(oc[nb][0], oc[nb][1]);
            *(float2*)(po + (r0+8)*DIM + col) = make_float2(oc[nb][2], oc[nb][3]);
        }
    }
}

// =====================================================================
// FUSED combine + LN1 + FF1 GEMM (unchanged)
// =====================================================================
__global__ void __launch_bounds__(256) ff1_fused_kernel(
    const float* __restrict__ PO, const float* __restrict__ L,
    const float* __restrict__ XF, const float* __restrict__ lg,
    const float* __restrict__ lb,
    const float* __restrict__ W, const float* __restrict__ bias,
    float* __restrict__ H1, float* __restrict__ FFH)
{
    __shared__ float sA[64*68];
    __shared__ float sW[64*72];
    int t = threadIdx.x;
    int lane = t & 31, wid = t >> 5;
    int gid = lane >> 2, l4 = lane & 3;
    int mw = wid & 3, nw = wid >> 2;
    int rbase = blockIdx.x * 64;
    int cb    = blockIdx.y * 64;

    {
        int rr = t >> 2, s4 = t & 3;
        int row = rbase + rr;
        float inv = 1.f / (L[row] + L[NPTS + row] + L[2*NPTS + row]);
        const float* p0 = PO + row*DIM + s4*16;
        const float* p1 = PO + (NPTS + row)*DIM + s4*16;
        const float* p2 = PO + (2*NPTS + row)*DIM + s4*16;
        const float* xf = XF + row*DIM + s4*16;
        float v[16];
        #pragma unroll
        for (int q4 = 0; q4 < 4; q4++) {
            float4 a = *(const float4*)(p0 + q4*4);
            float4 b = *(const float4*)(p1 + q4*4);
            float4 c = *(const float4*)(p2 + q4*4);
            float4 x = *(const float4*)(xf + q4*4);
            v[q4*4+0] = (a.x + b.x + c.x)*inv + x.x;
            v[q4*4+1] = (a.y + b.y + c.y)*inv + x.y;
            v[q4*4+2] = (a.z + b.z + c.z)*inv + x.z;
            v[q4*4+3] = (a.w + b.w + c.w)*inv + x.w;
        }
        float s = 0.f, q = 0.f;
        #pragma unroll
        for (int i = 0; i < 16; i++) { s += v[i]; q += v[i]*v[i]; }
        s += __shfl_xor_sync(0xffffffffu, s, 1);
        s += __shfl_xor_sync(0xffffffffu, s, 2);
        q += __shfl_xor_sync(0xffffffffu, q, 1);
        q += __shfl_xor_sync(0xffffffffu, q, 2);
        float mu = s * (1.f/64.f);
        float istd = rsqrtf(q*(1.f/64.f) - mu*mu + EPSf);
        #pragma unroll
        for (int q4 = 0; q4 < 4; q4++) {
            float4 o;
            int c = s4*16 + q4*4;
            o.x = (v[q4*4+0]-mu)*istd*__ldg(lg+c  ) + __ldg(lb+c  );
            o.y = (v[q4*4+1]-mu)*istd*__ldg(lg+c+1) + __ldg(lb+c+1);
            o.z = (v[q4*4+2]-mu)*istd*__ldg(lg+c+2) + __ldg(lb+c+2);
            o.w = (v[q4*4+3]-mu)*istd*__ldg(lg+c+3) + __ldg(lb+c+3);
            *(float4*)(sA + rr*68 + c) = o;
            if (blockIdx.y == 0)
                *(float4*)(H1 + row*DIM + c) = o;
        }
    }
    #pragma unroll
    for (int it = 0; it < 4; it++) {
        int i = t + it*256, r = i >> 4, d4 = i & 15;
        *(float4*)(sW + r*72 + d4*4) = *(const float4*)(W + r*FFD + cb + d4*4);
    }
    __syncthreads();

    float acc[4][4];
    #pragma unroll
    for (int nb = 0; nb < 4; nb++)
        #pragma unroll
        for (int j = 0; j < 4; j++) acc[nb][j] = 0.f;

    int r0 = mw*16 + gid;
    #pragma unroll
    for (int ks = 0; ks < 8; ks++) {
        uint32_t a[4];
        int c0 = ks*8 + l4;
        a[0] = __float_as_uint(sA[ r0    *68 + c0    ]);
        a[1] = __float_as_uint(sA[(r0+8)*68 + c0    ]);
        a[2] = __float_as_uint(sA[ r0    *68 + c0 + 4]);
        a[3] = __float_as_uint(sA[(r0+8)*68 + c0 + 4]);
        #pragma unroll
        for (int nb = 0; nb < 4; nb++) {
            int dcol = nw*32 + nb*8 + gid;
            uint32_t b0 = __float_as_uint(sW[(ks*8 + l4    )*72 + dcol]);
            uint32_t b1 = __float_as_uint(sW[(ks*8 + l4 + 4)*72 + dcol]);
            mma_tf32(acc[nb], a, b0, b1);
        }
    }
    #pragma unroll
    for (int nb = 0; nb < 4; nb++) {
        int col = cb + nw*32 + nb*8 + l4*2;
        float b0 = __ldg(bias + col), b1 = __ldg(bias + col + 1);
        float v00 = fmaxf(0.f, acc[nb][0] + b0), v01 = fmaxf(0.f, acc[nb][1] + b1);
        float v10 = fmaxf(0.f, acc[nb][2] + b0), v11 = fmaxf(0.f, acc[nb][3] + b1);
        *(float2*)(FFH + (rbase + r0    )*FFD + col) = make_float2(v00, v01);
        *(float2*)(FFH + (rbase + r0 + 8)*FFD + col) = make_float2(v10, v11);
    }
}

// =====================================================================
// FF2 + residual + LN, 32 rows/block (unchanged)
// =====================================================================
__global__ void __launch_bounds__(256) ff2ln_tc_kernel(
    const float* __restrict__ FFH, const float* __restrict__ W,
    const float* __restrict__ bias, const float* __restrict__ H1,
    const float* __restrict__ lg, const float* __restrict__ lb,
    float* __restrict__ H2)
{
    __shared__ float sA[32*68];
    __shared__ float sW[64*72];
    int t = threadIdx.x;
    int lane = t & 31, wid = t >> 5;
    int gid = lane >> 2, l4 = lane & 3;
    int mw = wid & 1, nw = wid >> 1;
    int rbase = blockIdx.x * 32;
    int r0 = mw*16 + gid;

    float acc[2][4];
    #pragma unroll
    for (int nb = 0; nb < 2; nb++)
        #pragma unroll
        for (int j = 0; j < 4; j++) acc[nb][j] = 0.f;

    for (int kc = 0; kc < 4; kc++) {
        __syncthreads();
        #pragma unroll
        for (int it = 0; it < 2; it++) {
            int i = t + it*256, r = i >> 4, d4 = i & 15;
            *(float4*)(sA + r*68 + d4*4) =
                *(const float4*)(FFH + (rbase+r)*256 + kc*64 + d4*4);
        }
        #pragma unroll
        for (int it = 0; it < 4; it++) {
            int i = t + it*256, r = i >> 4, d4 = i & 15;
            *(float4*)(sW + r*72 + d4*4) =
                *(const float4*)(W + (kc*64 + r)*64 + d4*4);
        }
        __syncthreads();

        #pragma unroll
        for (int ks = 0; ks < 8; ks++) {
            uint32_t a[4];
            int c0 = ks*8 + l4;
            a[0] = __float_as_uint(sA[ r0    *68 + c0    ]);
            a[1] = __float_as_uint(sA[(r0+8)*68 + c0    ]);
            a[2] = __float_as_uint(sA[ r0    *68 + c0 + 4]);
            a[3] = __float_as_uint(sA[(r0+8)*68 + c0 + 4]);
            #pragma unroll
            for (int nb = 0; nb < 2; nb++) {
                int dcol = nw*16 + nb*8 + gid;
                uint32_t b0 = __float_as_uint(sW[(ks*8 + l4    )*72 + dcol]);
                uint32_t b1 = __float_as_uint(sW[(ks*8 + l4 + 4)*72 + dcol]);
                mma_tf32(acc[nb], a, b0, b1);
            }
        }
    }
    __syncthreads();

    #pragma unroll
    for (int nb = 0; nb < 2; nb++) {
        int col = nw*16 + nb*8 + l4*2;
        float b0 = __ldg(bias + col), b1 = __ldg(bias + col + 1);
        float2 h0 = *(const float2*)(H1 + (rbase + r0    )*64 + col);
        float2 h1v = *(const float2*)(H1 + (rbase + r0 + 8)*64 + col);
        sA[ r0    *68 + col    ] = acc[nb][0] + b0 + h0.x;
        sA[ r0    *68 + col + 1] = acc[nb][1] + b1 + h0.y;
        sA[(r0+8)*68 + col    ] = acc[nb][2] + b0 + h1v.x;
        sA[(r0+8)*68 + col + 1] = acc[nb][3] + b1 + h1v.y;
    }
    __syncthreads();

    {
        int rr = t >> 3, s8 = t & 7;
        float v[8];
        #pragma unroll
        for (int i = 0; i < 8; i++) v[i] = sA[rr*68 + s8*8 + i];
        float s = 0.f, q = 0.f;
        #pragma unroll
        for (int i = 0; i < 8; i++) { s += v[i]; q += v[i]*v[i]; }
        s += __shfl_xor_sync(0xffffffffu, s, 1);
        s += __shfl_xor_sync(0xffffffffu, s, 2);
        s += __shfl_xor_sync(0xffffffffu, s, 4);
        q += __shfl_xor_sync(0xffffffffu, q, 1);
        q += __shfl_xor_sync(0xffffffffu, q, 2);
        q += __shfl_xor_sync(0xffffffffu, q, 4);
        float mu = s * (1.f/64.f);
        float istd = rsqrtf(q*(1.f/64.f) - mu*mu + EPSf);
        float* op = H2 + (rbase + rr)*64 + s8*8;
        #pragma unroll
        for (int q4 = 0; q4 < 2; q4++) {
            float4 o;
            int c = s8*8 + q4*4;
            o.x = (v[q4*4+0]-mu)*istd*__ldg(lg+c  ) + __ldg(lb+c  );
            o.y = (v[q4*4+1]-mu)*istd*__ldg(lg+c+1) + __ldg(lb+c+1);
            o.z = (v[q4*4+2]-mu)*istd*__ldg(lg+c+2) + __ldg(lb+c+2);
            o.w = (v[q4*4+3]-mu)*istd*__ldg(lg+c+3) + __ldg(lb+c+3);
            *(float4*)(op + q4*4) = o;
        }
    }
}

// =====================================================================
// Fused meanshift (unchanged)
// =====================================================================
#define TJ 1024
__global__ void __launch_bounds__(256) meanshift_kernel(
    const float* __restrict__ X, const float* __restrict__ Y,
    const float* __restrict__ part,
    const float* __restrict__ bng, const float* __restrict__ bnb,
    const float* __restrict__ w2, const float* __restrict__ b2,
    float* __restrict__ Xout)
{
    __shared__ float4 sX[TJ];
    __shared__ float sstat[128];
    int t = threadIdx.x, lane = t & 31, wid = t >> 5;
    int i0 = blockIdx.x*16 + wid*2;

    if (t < 64) {
        float s1 = 0.f, s2 = 0.f;
        #pragma unroll 8
        for (int b = 0; b < 96; b++) {
            s1 += part[b*128 + t];
            s2 += part[b*128 + 64 + t];
        }
        float mu  = s1 * (1.f/(float)NPTS);
        float var = s2 * (1.f/(float)NPTS) - mu*mu;
        sstat[t]      = mu;
        sstat[64 + t] = rsqrtf(var + EPSf);
    }
    __syncthreads();

    float wq[2][3];
    #pragma unroll
    for (int it2 = 0; it2 < 2; it2++) {
        int i = i0 + it2;
        int c1 = lane, c2 = lane + 32;
        float yv1 = Y[i*64 + c1], yv2 = Y[i*64 + c2];
        float z1 = fmaxf(0.f, (yv1 - sstat[c1]) * sstat[64 + c1] * bng[c1] + bnb[c1]);
        float z2 = fmaxf(0.f, (yv2 - sstat[c2]) * sstat[64 + c2] * bng[c2] + bnb[c2]);
        float l[3];
        #pragma unroll
        for (int j = 0; j < 3; j++) {
            float p = z1*__ldg(w2 + c1*3 + j) + z2*__ldg(w2 + c2*3 + j);
            #pragma unroll
            for (int o = 16; o; o >>= 1) p += __shfl_xor_sync(0xffffffffu, p, o);
            l[j] = p + __ldg(b2 + j);
        }
        float mx = fmaxf(l[0], fmaxf(l[1], l[2]));
        float e0 = __expf(l[0]-mx), e1 = __expf(l[1]-mx), e2 = __expf(l[2]-mx);
        float inv = 1.f / (e0 + e1 + e2);
        wq[it2][0] = e0*inv; wq[it2][1] = e1*inv; wq[it2][2] = e2*inv;
    }

    float xa0 = X[i0*3], xa1 = X[i0*3+1], xa2 = X[i0*3+2];
    float xb0 = X[i0*3+3], xb1 = X[i0*3+4], xb2 = X[i0*3+5];
    float sqa = xa0*xa0 + xa1*xa1 + xa2*xa2;
    float sqb = xb0*xb0 + xb1*xb1 + xb2*xb2;

    float A0x=0,A0y=0,A0z=0,Ac0=0, A1x=0,A1y=0,A1z=0,Ac1=0, A2x=0,A2y=0,A2z=0,Ac2=0;
    float B0x=0,B0y=0,B0z=0,Bc0=0, B1x=0,B1y=0,B1z=0,Bc1=0, B2x=0,B2y=0,B2z=0,Bc2=0;

    for (int tile = 0; tile < NPTS/TJ; tile++) {
        __syncthreads();
        for (int u = t; u < TJ; u += 256) {
            const float* xp = X + (tile*TJ + u)*3;
            float x0 = xp[0], x1 = xp[1], x2 = xp[2];
            sX[u] = make_float4(x0, x1, x2, x0*x0 + x1*x1 + x2*x2);
        }
        __syncthreads();
        #pragma unroll 4
        for (int s = 0; s < TJ/32; s++) {
            float4 p = sX[s*32 + lane];
            {
                float dot = xa0*p.x + xa1*p.y + xa2*p.z;
                float d2 = fmaf(-2.f, dot, sqa + p.w);
                if (d2 <= 1.0f) {
                    A2x += p.x; A2y += p.y; A2z += p.z; Ac2 += 1.f;
                    if (d2 <= 0.25f) {
                        A1x += p.x; A1y += p.y; A1z += p.z; Ac1 += 1.f;
                        if (d2 <= 0.04f) {
                            A0x += p.x; A0y += p.y; A0z += p.z; Ac0 += 1.f;
                        }
                    }
                }
            }
            {
                float dot = xb0*p.x + xb1*p.y + xb2*p.z;
                float d2 = fmaf(-2.f, dot, sqb + p.w);
                if (d2 <= 1.0f) {
                    B2x += p.x; B2y += p.y; B2z += p.z; Bc2 += 1.f;
                    if (d2 <= 0.25f) {
                        B1x += p.x; B1y += p.y; B1z += p.z; Bc1 += 1.f;
                        if (d2 <= 0.04f) {
                            B0x += p.x; B0y += p.y; B0z += p.z; Bc0 += 1.f;
                        }
                    }
                }
            }
        }
    }
    #define WRED(v) { _Pragma("unroll") for (int o = 16; o; o >>= 1) v += __shfl_xor_sync(0xffffffffu, v, o); }
    WRED(A0x) WRED(A0y) WRED(A0z) WRED(Ac0)
    WRED(A1x) WRED(A1y) WRED(A1z) WRED(Ac1)
    WRED(A2x) WRED(A2y) WRED(A2z) WRED(Ac2)
    WRED(B0x) WRED(B0y) WRED(B0z) WRED(Bc0)
    WRED(B1x) WRED(B1y) WRED(B1z) WRED(Bc1)
    WRED(B2x) WRED(B2y) WRED(B2z) WRED(Bc2)
    #undef WRED
    if (lane == 0) {
        {
            float w0 = wq[0][0], w1 = wq[0][1], w2v = wq[0][2];
            float inv = 1.f / (w0 + w1 + w2v);
            float r0 = 1.f/Ac0, r1 = 1.f/Ac1, r2 = 1.f/Ac2;
            Xout[i0*3+0] = (A0x*r0*w0 + A1x*r1*w1 + A2x*r2*w2v) * inv;
            Xout[i0*3+1] = (A0y*r0*w0 + A1y*r1*w1 + A2y*r2*w2v) * inv;
            Xout[i0*3+2] = (A0z*r0*w0 + A1z*r1*w1 + A2z*r2*w2v) * inv;
        }
        {
            float w0 = wq[1][0], w1 = wq[1][1], w2v = wq[1][2];
            float inv = 1.f / (w0 + w1 + w2v);
            float r0 = 1.f/Bc0, r1 = 1.f/Bc1, r2 = 1.f/Bc2;
            Xout[i0*3+3] = (B0x*r0*w0 + B1x*r1*w1 + B2x*r2*w2v) * inv;
            Xout[i0*3+4] = (B0y*r0*w0 + B1y*r1*w1 + B2y*r2*w2v) * inv;
            Xout[i0*3+5] = (B0z*r0*w0 + B1z*r1*w1 + B2z*r2*w2v) * inv;
        }
    }
}

// =====================================================================
extern "C" void kernel_launch(void* const* d_in, const int* in_sizes, int n_in,
                              void* d_out, int out_size)
{
    (void)in_sizes; (void)n_in; (void)out_size;
    const float* x      = (const float*)d_in[0];
    const float* rg_fea = (const float*)d_in[1];
    const float* x_fea  = (const float*)d_in[2];
    const float* qp_w   = (const float*)d_in[3];
    const float* qp_b   = (const float*)d_in[4];
    const float* ln_g   = (const float*)d_in[5];
    const float* ln_b   = (const float*)d_in[6];
    const float* ff_w1  = (const float*)d_in[7];
    const float* ff_b1  = (const float*)d_in[8];
    const float* ff_w2  = (const float*)d_in[9];
    const float* ff_b2  = (const float*)d_in[10];
    const float* bw_w1  = (const float*)d_in[11];
    const float* bw_b1  = (const float*)d_in[12];
    const float* bn_g   = (const float*)d_in[13];
    const float* bn_b   = (const float*)d_in[14];
    const float* bw_w2  = (const float*)d_in[15];
    const float* bw_b2  = (const float*)d_in[16];
    float* out = (float*)d_out;

    uint32_t *p_qkh, *p_vth;
    float *p_h1, *p_h2, *p_ffh, *p_y, *p_xa, *p_po, *p_l, *p_part;
    cudaGetSymbolAddress((void**)&p_qkh,  g_qkh);
    cudaGetSymbolAddress((void**)&p_vth,  g_vth);
    cudaGetSymbolAddress((void**)&p_h1,   g_h1);
    cudaGetSymbolAddress((void**)&p_h2,   g_h2);
    cudaGetSymbolAddress((void**)&p_ffh,  g_ffh);
    cudaGetSymbolAddress((void**)&p_y,    g_y);
    cudaGetSymbolAddress((void**)&p_xa,   g_xa);
    cudaGetSymbolAddress((void**)&p_po,   g_po);
    cudaGetSymbolAddress((void**)&p_l,    g_l);
    cudaGetSymbolAddress((void**)&p_part, g_part);

    cudaFuncSetAttribute(flash_tc_kernel,
                         cudaFuncAttributeMaxDynamicSharedMemorySize, SMEM_FLASH);

    // attention block
    vpack_kernel<<<NPTS/64, 256>>>(x_fea, p_vth);
    gemm_qk_bf16_kernel<<<NPTS/64, 256>>>(rg_fea, qp_w, qp_b, p_qkh);
    flash_tc_kernel<<<dim3(NPTS/FQB, FSPLIT), 256, SMEM_FLASH>>>(
        (const __nv_bfloat16*)p_qkh, p_vth, p_po, p_l);
    ff1_fused_kernel<<<dim3(NPTS/64,4), 256>>>(p_po, p_l, x_fea, ln_g, ln_b,
                                               ff_w1, ff_b1, p_h1, p_ffh);
    ff2ln_tc_kernel<<<NPTS/32, 256>>>(p_ffh, ff_w2, ff_b2, p_h1, ln_g, ln_b, p_h2);

    // meanshift iterations
    for (int it = 0; it < 2; it++) {
        gemm_tc_kernel<64,false,true><<<dim3(NPTS/64,1), 256>>>(p_h2, bw_w1 + it*64*64,
                                                                bw_b1 + it*64, p_y, p_part);
        const float* src = (it == 0) ? x : p_xa;
        float* dst       = (it == 0) ? p_xa : out;
        meanshift_kernel<<<NPTS/16, 256>>>(src, p_y, p_part,
                                           bn_g + it*64, bn_b + it*64,
                                           bw_w2 + it*64*3, bw_b2 + it*3, dst);
    }
}

// round 16
// speedup vs baseline: 1.0252x; 1.0252x over previous
#include <cuda_runtime.h>
#include <cuda_bf16.h>
#include <math.h>
#include <stdint.h>

#define NPTS 6144
#define DIM  64
#define FFD  256
#define EPSf 1e-5f

// ---------------- device scratch (no allocations allowed) ----------------
__device__ uint32_t g_qkh[NPTS*32];     // qk projection, bf16x2 packed [row][kp]
__device__ uint32_t g_vth[64*(NPTS/2)]; // V transposed+packed: [d][kp]
__device__ float g_h1 [NPTS*DIM];
__device__ float g_h2 [NPTS*DIM];
__device__ float g_ffh[NPTS*FFD];
__device__ float g_y  [NPTS*DIM];
__device__ float g_xa [NPTS*3];
__device__ float g_po [6*NPTS*DIM];     // flash split partials (6 splits)
__device__ float g_l  [6*NPTS];
__device__ float g_part[96*128];

#define KPTOT (NPTS/2)   // 3072 kp words per d-row of Vt

// =====================================================================
// mma / ldmatrix helpers
// =====================================================================
__device__ __forceinline__ void mma_tf32(float c[4], const uint32_t a[4],
                                         uint32_t b0, uint32_t b1) {
    asm volatile(
        "mma.sync.aligned.m16n8k8.row.col.f32.tf32.tf32.f32 "
        "{%0,%1,%2,%3}, {%4,%5,%6,%7}, {%8,%9}, {%0,%1,%2,%3};"
        : "+f"(c[0]), "+f"(c[1]), "+f"(c[2]), "+f"(c[3])
        : "r"(a[0]), "r"(a[1]), "r"(a[2]), "r"(a[3]), "r"(b0), "r"(b1));
}

__device__ __forceinline__ void mma_bf16(float c[4], const uint32_t a[4],
                                         uint32_t b0, uint32_t b1) {
    asm volatile(
        "mma.sync.aligned.m16n8k16.row.col.f32.bf16.bf16.f32 "
        "{%0,%1,%2,%3}, {%4,%5,%6,%7}, {%8,%9}, {%0,%1,%2,%3};"
        : "+f"(c[0]), "+f"(c[1]), "+f"(c[2]), "+f"(c[3])
        : "r"(a[0]), "r"(a[1]), "r"(a[2]), "r"(a[3]), "r"(b0), "r"(b1));
}

__device__ __forceinline__ void ldsm4(uint32_t d[4], uint32_t saddr) {
    asm volatile("ldmatrix.sync.aligned.m8n8.x4.shared.b16 {%0,%1,%2,%3}, [%4];"
        : "=r"(d[0]), "=r"(d[1]), "=r"(d[2]), "=r"(d[3]) : "r"(saddr));
}

__device__ __forceinline__ void cpa16g(void* sdst, const void* gsrc) {
    uint32_t sa = (uint32_t)__cvta_generic_to_shared(sdst);
    asm volatile("cp.async.cg.shared.global [%0], [%1], 16;" :: "r"(sa), "l"(gsrc));
}

// =====================================================================
// PREP: blocks 0..95  -> V pack+transpose (Vt[d][kp])
//       blocks 96..191 -> QK projection GEMM, bf16x2-packed output
// =====================================================================
__global__ void __launch_bounds__(256) prep_kernel(
    const float* __restrict__ V, uint32_t* __restrict__ Vt,
    const float* __restrict__ A, const float* __restrict__ W,
    const float* __restrict__ bias, uint32_t* __restrict__ Ch)
{
    __shared__ float sA[64*68];
    __shared__ float sW[64*72];
    int t = threadIdx.x;

    if (blockIdx.x < 96) {
        // ---- vpack path (uses sA as the staging tile) ----
        int rbase = blockIdx.x * 64;
        int kpb   = blockIdx.x * 32;
        #pragma unroll
        for (int it = 0; it < 4; it++) {
            int i = t + it*256, r = i >> 4, d4 = i & 15;
            *(float4*)(sA + r*68 + d4*4) = *(const float4*)(V + (rbase+r)*64 + d4*4);
        }
        __syncthreads();
        int d = t >> 2, g = t & 3;
        #pragma unroll
        for (int j = 0; j < 8; j++) {
            int kp = g*8 + j;
            __nv_bfloat162 h = __floats2bfloat162_rn(sA[(2*kp)*68 + d], sA[(2*kp+1)*68 + d]);
            Vt[d*KPTOT + kpb + kp] = *(uint32_t*)&h;
        }
        return;
    }

    // ---- QK projection path ----
    int lane = t & 31, wid = t >> 5;
    int gid = lane >> 2, l4 = lane & 3;
    int mw = wid & 3, nw = wid >> 2;
    int rbase = (blockIdx.x - 96) * 64;

    #pragma unroll
    for (int it = 0; it < 4; it++) {
        int i = t + it*256, r = i >> 4, d4 = i & 15;
        *(float4*)(sA + r*68 + d4*4) = *(const float4*)(A + (rbase+r)*64 + d4*4);
        *(float4*)(sW + r*72 + d4*4) = *(const float4*)(W + r*64 + d4*4);
    }
    __syncthreads();

    float acc[4][4];
    #pragma unroll
    for (int nb = 0; nb < 4; nb++)
        #pragma unroll
        for (int j = 0; j < 4; j++) acc[nb][j] = 0.f;

    int r0 = mw*16 + gid;
    #pragma unroll
    for (int ks = 0; ks < 8; ks++) {
        uint32_t a[4];
        int c0 = ks*8 + l4;
        a[0] = __float_as_uint(sA[ r0    *68 + c0    ]);
        a[1] = __float_as_uint(sA[(r0+8)*68 + c0    ]);
        a[2] = __float_as_uint(sA[ r0    *68 + c0 + 4]);
        a[3] = __float_as_uint(sA[(r0+8)*68 + c0 + 4]);
        #pragma unroll
        for (int nb = 0; nb < 4; nb++) {
            int dcol = nw*32 + nb*8 + gid;
            uint32_t b0 = __float_as_uint(sW[(ks*8 + l4    )*72 + dcol]);
            uint32_t b1 = __float_as_uint(sW[(ks*8 + l4 + 4)*72 + dcol]);
            mma_tf32(acc[nb], a, b0, b1);
        }
    }
    #pragma unroll
    for (int nb = 0; nb < 4; nb++) {
        int col = nw*32 + nb*8 + l4*2;
        float b0 = __ldg(bias + col), b1 = __ldg(bias + col + 1);
        __nv_bfloat162 h0 = __floats2bfloat162_rn(acc[nb][0] + b0, acc[nb][1] + b1);
        __nv_bfloat162 h1 = __floats2bfloat162_rn(acc[nb][2] + b0, acc[nb][3] + b1);
        Ch[(rbase + r0    )*32 + (col >> 1)] = *(uint32_t*)&h0;
        Ch[(rbase + r0 + 8)*32 + (col >> 1)] = *(uint32_t*)&h1;
    }
}

// =====================================================================
// Tensor-core GEMM (tf32): C = A@W + b ; opt relu; opt BN partials
// =====================================================================
template<int LDW, bool RELU, bool BNP>
__global__ void __launch_bounds__(256) gemm_tc_kernel(
    const float* __restrict__ A, const float* __restrict__ W,
    const float* __restrict__ bias, float* __restrict__ C,
    float* __restrict__ part)
{
    __shared__ float sA[64*68];
    __shared__ float sW[64*72];
    int t = threadIdx.x;
    int lane = t & 31, wid = t >> 5;
    int gid = lane >> 2, l4 = lane & 3;
    int mw = wid & 3, nw = wid >> 2;
    int rbase = blockIdx.x * 64;
    int cb    = blockIdx.y * 64;

    #pragma unroll
    for (int it = 0; it < 4; it++) {
        int i = t + it*256, r = i >> 4, d4 = i & 15;
        *(float4*)(sA + r*68 + d4*4) = *(const float4*)(A + (rbase+r)*64 + d4*4);
        *(float4*)(sW + r*72 + d4*4) = *(const float4*)(W + r*LDW + cb + d4*4);
    }
    __syncthreads();

    float acc[4][4];
    #pragma unroll
    for (int nb = 0; nb < 4; nb++)
        #pragma unroll
        for (int j = 0; j < 4; j++) acc[nb][j] = 0.f;

    int r0 = mw*16 + gid;
    #pragma unroll
    for (int ks = 0; ks < 8; ks++) {
        uint32_t a[4];
        int c0 = ks*8 + l4;
        a[0] = __float_as_uint(sA[ r0    *68 + c0    ]);
        a[1] = __float_as_uint(sA[(r0+8)*68 + c0    ]);
        a[2] = __float_as_uint(sA[ r0    *68 + c0 + 4]);
        a[3] = __float_as_uint(sA[(r0+8)*68 + c0 + 4]);
        #pragma unroll
        for (int nb = 0; nb < 4; nb++) {
            int dcol = nw*32 + nb*8 + gid;
            uint32_t b0 = __float_as_uint(sW[(ks*8 + l4    )*72 + dcol]);
            uint32_t b1 = __float_as_uint(sW[(ks*8 + l4 + 4)*72 + dcol]);
            mma_tf32(acc[nb], a, b0, b1);
        }
    }

    if (BNP) __syncthreads();
    float* sp1 = sW;
    float* sp2 = sW + 2048;

    #pragma unroll
    for (int nb = 0; nb < 4; nb++) {
        int col = cb + nw*32 + nb*8 + l4*2;
        float b0 = __ldg(bias + col), b1 = __ldg(bias + col + 1);
        float v00 = acc[nb][0] + b0, v01 = acc[nb][1] + b1;
        float v10 = acc[nb][2] + b0, v11 = acc[nb][3] + b1;
        if (RELU) {
            v00 = fmaxf(0.f, v00); v01 = fmaxf(0.f, v01);
            v10 = fmaxf(0.f, v10); v11 = fmaxf(0.f, v11);
        }
        *(float2*)(C + (rbase + r0    )*LDW + col) = make_float2(v00, v01);
        *(float2*)(C + (rbase + r0 + 8)*LDW + col) = make_float2(v10, v11);
        if (BNP) {
            int lc = nw*32 + nb*8 + l4*2;
            int slot = (mw*8 + gid)*64;
            sp1[slot + lc    ] = v00 + v10;
            sp1[slot + lc + 1] = v01 + v11;
            sp2[slot + lc    ] = v00*v00 + v10*v10;
            sp2[slot + lc + 1] = v01*v01 + v11*v11;
        }
    }
    if (BNP) {
        __syncthreads();
        if (t < 64) {
            float s1 = 0.f, s2 = 0.f;
            #pragma unroll 8
            for (int k = 0; k < 32; k++) {
                s1 += sp1[k*64 + t];
                s2 += sp2[k*64 + t];
            }
            part[blockIdx.x*128 + t]      = s1;
            part[blockIdx.x*128 + 64 + t] = s2;
        }
    }
}

// =====================================================================
// Split-K flash v5: FSPLIT=6 (288 blocks -> ~2/SM co-residency),
// FQB=128, registers-only P, ldmatrix B-operands.
// =====================================================================
#define FQB 128
#define FKB 64
#define FSPLIT 6
#define FTILES (NPTS/FKB/FSPLIT)   // 16
#define SKH 36

#define SMEM_FLASH ((2*64*SKH + 2*64*SKH + 128*SKH) * 4)

__global__ void __launch_bounds__(256, 2) flash_tc_kernel(
    const __nv_bfloat16* __restrict__ Qh, const uint32_t* __restrict__ Vt,
    float* __restrict__ PO, float* __restrict__ Lout)
{
    extern __shared__ float sm[];
    uint32_t* sKb = (uint32_t*)sm;
    uint32_t* sVb = (uint32_t*)sm + 2*64*SKH;
    uint32_t* sQ  = (uint32_t*)sm + 4*64*SKH;

    int t = threadIdx.x;
    int lane = t & 31, wid = t >> 5;
    int gid = lane >> 2, l4 = lane & 3;
    int m8 = lane >> 3, r8 = lane & 7;
    int qbase = blockIdx.x * FQB;
    int split = blockIdx.y;
    int ktbase = split * FTILES;

    uint32_t boff = (((m8 >> 1)*8 + r8)*SKH + (m8 & 1)*4) * 4;
    uint32_t aoff = (((m8 & 1)*8 + r8)*SKH + (m8 >> 1)*4) * 4;

    // ---- prologue ----
    {
        #pragma unroll
        for (int it = 0; it < 4; it++) {
            int idx = t + it*256, r = idx >> 3, c = idx & 7;
            cpa16g(sQ + r*SKH + c*4, Qh + (qbase + r)*64 + c*8);
        }
        #pragma unroll
        for (int it = 0; it < 2; it++) {
            int idx = t + it*256, r = idx >> 3, c = idx & 7;
            cpa16g(sKb + r*SKH + c*4, Qh + (ktbase*FKB + r)*64 + c*8);
        }
        #pragma unroll
        for (int it = 0; it < 2; it++) {
            int idx = t + it*256, d = idx >> 3, c = idx & 7;
            cpa16g(sVb + d*SKH + c*4, Vt + d*KPTOT + ktbase*32 + c*4);
        }
        asm volatile("cp.async.commit_group;");
        asm volatile("cp.async.wait_group 0;");
    }
    __syncthreads();

    int r0 = wid*16 + gid;
    uint32_t qa[4][4];
    {
        uint32_t sQl = (uint32_t)__cvta_generic_to_shared(sQ) + wid*16*SKH*4 + aoff;
        #pragma unroll
        for (int ks = 0; ks < 4; ks++)
            ldsm4(qa[ks], sQl + ks*8*4);
    }

    float oc[8][4];
    #pragma unroll
    for (int nb = 0; nb < 8; nb++)
        #pragma unroll
        for (int j = 0; j < 4; j++) oc[nb][j] = 0.f;
    float rs0 = 0.f, rs1 = 0.f;

    uint32_t sK0 = (uint32_t)__cvta_generic_to_shared(sKb);
    uint32_t sV0 = (uint32_t)__cvta_generic_to_shared(sVb);

    for (int kt = 0; kt < FTILES; kt++) {
        int cur = kt & 1;
        uint32_t sKl = sK0 + cur*64*SKH*4 + boff;
        uint32_t sVl = sV0 + cur*64*SKH*4 + boff;

        __syncthreads();
        if (kt + 1 < FTILES) {
            const __nv_bfloat16* Kt = Qh + (ktbase + kt + 1)*FKB*DIM;
            const uint32_t* Vn = Vt + (ktbase + kt + 1)*32;
            uint32_t* dK = sKb + (cur^1)*64*SKH;
            uint32_t* dV = sVb + (cur^1)*64*SKH;
            #pragma unroll
            for (int it = 0; it < 2; it++) {
                int idx = t + it*256, r = idx >> 3, c = idx & 7;
                cpa16g(dK + r*SKH + c*4, Kt + r*64 + c*8);
            }
            #pragma unroll
            for (int it = 0; it < 2; it++) {
                int idx = t + it*256, d = idx >> 3, c = idx & 7;
                cpa16g(dV + d*SKH + c*4, Vn + d*KPTOT + c*4);
            }
            asm volatile("cp.async.commit_group;");
            asm volatile("cp.async.wait_group 1;");
        } else {
            asm volatile("cp.async.wait_group 0;");
        }
        __syncthreads();

        // ---- S = Q @ K^T ----
        float sc[8][4];
        #pragma unroll
        for (int nb = 0; nb < 8; nb++)
            #pragma unroll
            for (int j = 0; j < 4; j++) sc[nb][j] = 0.f;

        #pragma unroll
        for (int ks = 0; ks < 4; ks++) {
            #pragma unroll
            for (int nbp = 0; nbp < 4; nbp++) {
                uint32_t kb[4];
                ldsm4(kb, sKl + (nbp*16*SKH + ks*8)*4);
                mma_bf16(sc[2*nbp    ], qa[ks], kb[0], kb[1]);
                mma_bf16(sc[2*nbp + 1], qa[ks], kb[2], kb[3]);
            }
        }

        // ---- P = exp(S/8); pack to PV A-fragments ----
        uint32_t pa[4][4];
        #pragma unroll
        for (int nb = 0; nb < 8; nb++) {
            float p0 = __expf(sc[nb][0]*0.125f);
            float p1 = __expf(sc[nb][1]*0.125f);
            float p2 = __expf(sc[nb][2]*0.125f);
            float p3 = __expf(sc[nb][3]*0.125f);
            rs0 += p0 + p1;
            rs1 += p2 + p3;
            __nv_bfloat162 h0 = __floats2bfloat162_rn(p0, p1);
            __nv_bfloat162 h1 = __floats2bfloat162_rn(p2, p3);
            int ks = nb >> 1, hf = (nb & 1)*2;
            pa[ks][hf    ] = *(uint32_t*)&h0;
            pa[ks][hf + 1] = *(uint32_t*)&h1;
        }

        // ---- O += P @ V ----
        #pragma unroll
        for (int ks = 0; ks < 4; ks++) {
            #pragma unroll
            for (int nbp = 0; nbp < 4; nbp++) {
                uint32_t vb[4];
                ldsm4(vb, sVl + (nbp*16*SKH + ks*8)*4);
                mma_bf16(oc[2*nbp    ], pa[ks], vb[0], vb[1]);
                mma_bf16(oc[2*nbp + 1], pa[ks], vb[2], vb[3]);
            }
        }
    }

    rs0 += __shfl_xor_sync(0xffffffffu, rs0, 1);
    rs0 += __shfl_xor_sync(0xffffffffu, rs0, 2);
    rs1 += __shfl_xor_sync(0xffffffffu, rs1, 1);
    rs1 += __shfl_xor_sync(0xffffffffu, rs1, 2);
    if (l4 == 0) {
        Lout[split*NPTS + qbase + r0    ] = rs0;
        Lout[split*NPTS + qbase + r0 + 8] = rs1;
    }
    {
        float* po = PO + (split*NPTS + qbase)*DIM;
        #pragma unroll
        for (int nb = 0; nb < 8; nb++) {
            int col = nb*8 + l4*2;
            *(float2*)(po +  r0    *DIM + col) = make_float2(oc[nb][0], oc[nb][1]);
            *(float2*)(po + (r0+8)*DIM + col) = make_float2(oc[nb][2], oc[nb][3]);
        }
    }
}

// =====================================================================
// FUSED combine (6 splits) + LN1 + FF1 GEMM
// =====================================================================
__global__ void __launch_bounds__(256) ff1_fused_kernel(
    const float* __restrict__ PO, const float* __restrict__ L,
    const float* __restrict__ XF, const float* __restrict__ lg,
    const float* __restrict__ lb,
    const float* __restrict__ W, const float* __restrict__ bias,
    float* __restrict__ H1, float* __restrict__ FFH)
{
    __shared__ float sA[64*68];
    __shared__ float sW[64*72];
    int t = threadIdx.x;
    int lane = t & 31, wid = t >> 5;
    int gid = lane >> 2, l4 = lane & 3;
    int mw = wid & 3, nw = wid >> 2;
    int rbase = blockIdx.x * 64;
    int cb    = blockIdx.y * 64;

    {
        int rr = t >> 2, s4 = t & 3;
        int row = rbase + rr;
        float lsum = 0.f;
        #pragma unroll
        for (int s = 0; s < FSPLIT; s++) lsum += L[s*NPTS + row];
        float inv = 1.f / lsum;
        const float* xf = XF + row*DIM + s4*16;
        float v[16];
        #pragma unroll
        for (int q4 = 0; q4 < 4; q4++) {
            float ax = 0.f, ay = 0.f, az = 0.f, aw = 0.f;
            #pragma unroll
            for (int s = 0; s < FSPLIT; s++) {
                float4 a = *(const float4*)(PO + (s*NPTS + row)*DIM + s4*16 + q4*4);
                ax += a.x; ay += a.y; az += a.z; aw += a.w;
            }
            float4 x = *(const float4*)(xf + q4*4);
            v[q4*4+0] = ax*inv + x.x;
            v[q4*4+1] = ay*inv + x.y;
            v[q4*4+2] = az*inv + x.z;
            v[q4*4+3] = aw*inv + x.w;
        }
        float s = 0.f, q = 0.f;
        #pragma unroll
        for (int i = 0; i < 16; i++) { s += v[i]; q += v[i]*v[i]; }
        s += __shfl_xor_sync(0xffffffffu, s, 1);
        s += __shfl_xor_sync(0xffffffffu, s, 2);
        q += __shfl_xor_sync(0xffffffffu, q, 1);
        q += __shfl_xor_sync(0xffffffffu, q, 2);
        float mu = s * (1.f/64.f);
        float istd = rsqrtf(q*(1.f/64.f) - mu*mu + EPSf);
        #pragma unroll
        for (int q4 = 0; q4 < 4; q4++) {
            float4 o;
            int c = s4*16 + q4*4;
            o.x = (v[q4*4+0]-mu)*istd*__ldg(lg+c  ) + __ldg(lb+c  );
            o.y = (v[q4*4+1]-mu)*istd*__ldg(lg+c+1) + __ldg(lb+c+1);
            o.z = (v[q4*4+2]-mu)*istd*__ldg(lg+c+2) + __ldg(lb+c+2);
            o.w = (v[q4*4+3]-mu)*istd*__ldg(lg+c+3) + __ldg(lb+c+3);
            *(float4*)(sA + rr*68 + c) = o;
            if (blockIdx.y == 0)
                *(float4*)(H1 + row*DIM + c) = o;
        }
    }
    #pragma unroll
    for (int it = 0; it < 4; it++) {
        int i = t + it*256, r = i >> 4, d4 = i & 15;
        *(float4*)(sW + r*72 + d4*4) = *(const float4*)(W + r*FFD + cb + d4*4);
    }
    __syncthreads();

    float acc[4][4];
    #pragma unroll
    for (int nb = 0; nb < 4; nb++)
        #pragma unroll
        for (int j = 0; j < 4; j++) acc[nb][j] = 0.f;

    int r0 = mw*16 + gid;
    #pragma unroll
    for (int ks = 0; ks < 8; ks++) {
        uint32_t a[4];
        int c0 = ks*8 + l4;
        a[0] = __float_as_uint(sA[ r0    *68 + c0    ]);
        a[1] = __float_as_uint(sA[(r0+8)*68 + c0    ]);
        a[2] = __float_as_uint(sA[ r0    *68 + c0 + 4]);
        a[3] = __float_as_uint(sA[(r0+8)*68 + c0 + 4]);
        #pragma unroll
        for (int nb = 0; nb < 4; nb++) {
            int dcol = nw*32 + nb*8 + gid;
            uint32_t b0 = __float_as_uint(sW[(ks*8 + l4    )*72 + dcol]);
            uint32_t b1 = __float_as_uint(sW[(ks*8 + l4 + 4)*72 + dcol]);
            mma_tf32(acc[nb], a, b0, b1);
        }
    }
    #pragma unroll
    for (int nb = 0; nb < 4; nb++) {
        int col = cb + nw*32 + nb*8 + l4*2;
        float b0 = __ldg(bias + col), b1 = __ldg(bias + col + 1);
        float v00 = fmaxf(0.f, acc[nb][0] + b0), v01 = fmaxf(0.f, acc[nb][1] + b1);
        float v10 = fmaxf(0.f, acc[nb][2] + b0), v11 = fmaxf(0.f, acc[nb][3] + b1);
        *(float2*)(FFH + (rbase + r0    )*FFD + col) = make_float2(v00, v01);
        *(float2*)(FFH + (rbase + r0 + 8)*FFD + col) = make_float2(v10, v11);
    }
}

// =====================================================================
// FF2 + residual + LN, 32 rows/block (unchanged)
// =====================================================================
__global__ void __launch_bounds__(256) ff2ln_tc_kernel(
    const float* __restrict__ FFH, const float* __restrict__ W,
    const float* __restrict__ bias, const float* __restrict__ H1,
    const float* __restrict__ lg, const float* __restrict__ lb,
    float* __restrict__ H2)
{
    __shared__ float sA[32*68];
    __shared__ float sW[64*72];
    int t = threadIdx.x;
    int lane = t & 31, wid = t >> 5;
    int gid = lane >> 2, l4 = lane & 3;
    int mw = wid & 1, nw = wid >> 1;
    int rbase = blockIdx.x * 32;
    int r0 = mw*16 + gid;

    float acc[2][4];
    #pragma unroll
    for (int nb = 0; nb < 2; nb++)
        #pragma unroll
        for (int j = 0; j < 4; j++) acc[nb][j] = 0.f;

    for (int kc = 0; kc < 4; kc++) {
        __syncthreads();
        #pragma unroll
        for (int it = 0; it < 2; it++) {
            int i = t + it*256, r = i >> 4, d4 = i & 15;
            *(float4*)(sA + r*68 + d4*4) =
                *(const float4*)(FFH + (rbase+r)*256 + kc*64 + d4*4);
        }
        #pragma unroll
        for (int it = 0; it < 4; it++) {
            int i = t + it*256, r = i >> 4, d4 = i & 15;
            *(float4*)(sW + r*72 + d4*4) =
                *(const float4*)(W + (kc*64 + r)*64 + d4*4);
        }
        __syncthreads();

        #pragma unroll
        for (int ks = 0; ks < 8; ks++) {
            uint32_t a[4];
            int c0 = ks*8 + l4;
            a[0] = __float_as_uint(sA[ r0    *68 + c0    ]);
            a[1] = __float_as_uint(sA[(r0+8)*68 + c0    ]);
            a[2] = __float_as_uint(sA[ r0    *68 + c0 + 4]);
            a[3] = __float_as_uint(sA[(r0+8)*68 + c0 + 4]);
            #pragma unroll
            for (int nb = 0; nb < 2; nb++) {
                int dcol = nw*16 + nb*8 + gid;
                uint32_t b0 = __float_as_uint(sW[(ks*8 + l4    )*72 + dcol]);
                uint32_t b1 = __float_as_uint(sW[(ks*8 + l4 + 4)*72 + dcol]);
                mma_tf32(acc[nb], a, b0, b1);
            }
        }
    }
    __syncthreads();

    #pragma unroll
    for (int nb = 0; nb < 2; nb++) {
        int col = nw*16 + nb*8 + l4*2;
        float b0 = __ldg(bias + col), b1 = __ldg(bias + col + 1);
        float2 h0 = *(const float2*)(H1 + (rbase + r0    )*64 + col);
        float2 h1v = *(const float2*)(H1 + (rbase + r0 + 8)*64 + col);
        sA[ r0    *68 + col    ] = acc[nb][0] + b0 + h0.x;
        sA[ r0    *68 + col + 1] = acc[nb][1] + b1 + h0.y;
        sA[(r0+8)*68 + col    ] = acc[nb][2] + b0 + h1v.x;
        sA[(r0+8)*68 + col + 1] = acc[nb][3] + b1 + h1v.y;
    }
    __syncthreads();

    {
        int rr = t >> 3, s8 = t & 7;
        float v[8];
        #pragma unroll
        for (int i = 0; i < 8; i++) v[i] = sA[rr*68 + s8*8 + i];
        float s = 0.f, q = 0.f;
        #pragma unroll
        for (int i = 0; i < 8; i++) { s += v[i]; q += v[i]*v[i]; }
        s += __shfl_xor_sync(0xffffffffu, s, 1);
        s += __shfl_xor_sync(0xffffffffu, s, 2);
        s += __shfl_xor_sync(0xffffffffu, s, 4);
        q += __shfl_xor_sync(0xffffffffu, q, 1);
        q += __shfl_xor_sync(0xffffffffu, q, 2);
        q += __shfl_xor_sync(0xffffffffu, q, 4);
        float mu = s * (1.f/64.f);
        float istd = rsqrtf(q*(1.f/64.f) - mu*mu + EPSf);
        float* op = H2 + (rbase + rr)*64 + s8*8;
        #pragma unroll
        for (int q4 = 0; q4 < 2; q4++) {
            float4 o;
            int c = s8*8 + q4*4;
            o.x = (v[q4*4+0]-mu)*istd*__ldg(lg+c  ) + __ldg(lb+c  );
            o.y = (v[q4*4+1]-mu)*istd*__ldg(lg+c+1) + __ldg(lb+c+1);
            o.z = (v[q4*4+2]-mu)*istd*__ldg(lg+c+2) + __ldg(lb+c+2);
            o.w = (v[q4*4+3]-mu)*istd*__ldg(lg+c+3) + __ldg(lb+c+3);
            *(float4*)(op + q4*4) = o;
        }
    }
}

// =====================================================================
// Fused meanshift (unchanged)
// =====================================================================
#define TJ 1024
__global__ void __launch_bounds__(256) meanshift_kernel(
    const float* __restrict__ X, const float* __restrict__ Y,
    const float* __restrict__ part,
    const float* __restrict__ bng, const float* __restrict__ bnb,
    const float* __restrict__ w2, const float* __restrict__ b2,
    float* __restrict__ Xout)
{
    __shared__ float4 sX[TJ];
    __shared__ float sstat[128];
    int t = threadIdx.x, lane = t & 31, wid = t >> 5;
    int i0 = blockIdx.x*16 + wid*2;

    if (t < 64) {
        float s1 = 0.f, s2 = 0.f;
        #pragma unroll 8
        for (int b = 0; b < 96; b++) {
            s1 += part[b*128 + t];
            s2 += part[b*128 + 64 + t];
        }
        float mu  = s1 * (1.f/(float)NPTS);
        float var = s2 * (1.f/(float)NPTS) - mu*mu;
        sstat[t]      = mu;
        sstat[64 + t] = rsqrtf(var + EPSf);
    }
    __syncthreads();

    float wq[2][3];
    #pragma unroll
    for (int it2 = 0; it2 < 2; it2++) {
        int i = i0 + it2;
        int c1 = lane, c2 = lane + 32;
        float yv1 = Y[i*64 + c1], yv2 = Y[i*64 + c2];
        float z1 = fmaxf(0.f, (yv1 - sstat[c1]) * sstat[64 + c1] * bng[c1] + bnb[c1]);
        float z2 = fmaxf(0.f, (yv2 - sstat[c2]) * sstat[64 + c2] * bng[c2] + bnb[c2]);
        float l[3];
        #pragma unroll
        for (int j = 0; j < 3; j++) {
            float p = z1*__ldg(w2 + c1*3 + j) + z2*__ldg(w2 + c2*3 + j);
            #pragma unroll
            for (int o = 16; o; o >>= 1) p += __shfl_xor_sync(0xffffffffu, p, o);
            l[j] = p + __ldg(b2 + j);
        }
        float mx = fmaxf(l[0], fmaxf(l[1], l[2]));
        float e0 = __expf(l[0]-mx), e1 = __expf(l[1]-mx), e2 = __expf(l[2]-mx);
        float inv = 1.f / (e0 + e1 + e2);
        wq[it2][0] = e0*inv; wq[it2][1] = e1*inv; wq[it2][2] = e2*inv;
    }

    float xa0 = X[i0*3], xa1 = X[i0*3+1], xa2 = X[i0*3+2];
    float xb0 = X[i0*3+3], xb1 = X[i0*3+4], xb2 = X[i0*3+5];
    float sqa = xa0*xa0 + xa1*xa1 + xa2*xa2;
    float sqb = xb0*xb0 + xb1*xb1 + xb2*xb2;

    float A0x=0,A0y=0,A0z=0,Ac0=0, A1x=0,A1y=0,A1z=0,Ac1=0, A2x=0,A2y=0,A2z=0,Ac2=0;
    float B0x=0,B0y=0,B0z=0,Bc0=0, B1x=0,B1y=0,B1z=0,Bc1=0, B2x=0,B2y=0,B2z=0,Bc2=0;

    for (int tile = 0; tile < NPTS/TJ; tile++) {
        __syncthreads();
        for (int u = t; u < TJ; u += 256) {
            const float* xp = X + (tile*TJ + u)*3;
            float x0 = xp[0], x1 = xp[1], x2 = xp[2];
            sX[u] = make_float4(x0, x1, x2, x0*x0 + x1*x1 + x2*x2);
        }
        __syncthreads();
        #pragma unroll 4
        for (int s = 0; s < TJ/32; s++) {
            float4 p = sX[s*32 + lane];
            {
                float dot = xa0*p.x + xa1*p.y + xa2*p.z;
                float d2 = fmaf(-2.f, dot, sqa + p.w);
                if (d2 <= 1.0f) {
                    A2x += p.x; A2y += p.y; A2z += p.z; Ac2 += 1.f;
                    if (d2 <= 0.25f) {
                        A1x += p.x; A1y += p.y; A1z += p.z; Ac1 += 1.f;
                        if (d2 <= 0.04f) {
                            A0x += p.x; A0y += p.y; A0z += p.z; Ac0 += 1.f;
                        }
                    }
                }
            }
            {
                float dot = xb0*p.x + xb1*p.y + xb2*p.z;
                float d2 = fmaf(-2.f, dot, sqb + p.w);
                if (d2 <= 1.0f) {
                    B2x += p.x; B2y += p.y; B2z += p.z; Bc2 += 1.f;
                    if (d2 <= 0.25f) {
                        B1x += p.x; B1y += p.y; B1z += p.z; Bc1 += 1.f;
                        if (d2 <= 0.04f) {
                            B0x += p.x; B0y += p.y; B0z += p.z; Bc0 += 1.f;
                        }
                    }
                }
            }
        }
    }
    #define WRED(v) { _Pragma("unroll") for (int o = 16; o; o >>= 1) v += __shfl_xor_sync(0xffffffffu, v, o); }
    WRED(A0x) WRED(A0y) WRED(A0z) WRED(Ac0)
    WRED(A1x) WRED(A1y) WRED(A1z) WRED(Ac1)
    WRED(A2x) WRED(A2y) WRED(A2z) WRED(Ac2)
    WRED(B0x) WRED(B0y) WRED(B0z) WRED(Bc0)
    WRED(B1x) WRED(B1y) WRED(B1z) WRED(Bc1)
    WRED(B2x) WRED(B2y) WRED(B2z) WRED(Bc2)
    #undef WRED
    if (lane == 0) {
        {
            float w0 = wq[0][0], w1 = wq[0][1], w2v = wq[0][2];
            float inv = 1.f / (w0 + w1 + w2v);
            float r0 = 1.f/Ac0, r1 = 1.f/Ac1, r2 = 1.f/Ac2;
            Xout[i0*3+0] = (A0x*r0*w0 + A1x*r1*w1 + A2x*r2*w2v) * inv;
            Xout[i0*3+1] = (A0y*r0*w0 + A1y*r1*w1 + A2y*r2*w2v) * inv;
            Xout[i0*3+2] = (A0z*r0*w0 + A1z*r1*w1 + A2z*r2*w2v) * inv;
        }
        {
            float w0 = wq[1][0], w1 = wq[1][1], w2v = wq[1][2];
            float inv = 1.f / (w0 + w1 + w2v);
            float r0 = 1.f/Bc0, r1 = 1.f/Bc1, r2 = 1.f/Bc2;
            Xout[i0*3+3] = (B0x*r0*w0 + B1x*r1*w1 + B2x*r2*w2v) * inv;
            Xout[i0*3+4] = (B0y*r0*w0 + B1y*r1*w1 + B2y*r2*w2v) * inv;
            Xout[i0*3+5] = (B0z*r0*w0 + B1z*r1*w1 + B2z*r2*w2v) * inv;
        }
    }
}

// =====================================================================
extern "C" void kernel_launch(void* const* d_in, const int* in_sizes, int n_in,
                              void* d_out, int out_size)
{
    (void)in_sizes; (void)n_in; (void)out_size;
    const float* x      = (const float*)d_in[0];
    const float* rg_fea = (const float*)d_in[1];
    const float* x_fea  = (const float*)d_in[2];
    const float* qp_w   = (const float*)d_in[3];
    const float* qp_b   = (const float*)d_in[4];
    const float* ln_g   = (const float*)d_in[5];
    const float* ln_b   = (const float*)d_in[6];
    const float* ff_w1  = (const float*)d_in[7];
    const float* ff_b1  = (const float*)d_in[8];
    const float* ff_w2  = (const float*)d_in[9];
    const float* ff_b2  = (const float*)d_in[10];
    const float* bw_w1  = (const float*)d_in[11];
    const float* bw_b1  = (const float*)d_in[12];
    const float* bn_g   = (const float*)d_in[13];
    const float* bn_b   = (const float*)d_in[14];
    const float* bw_w2  = (const float*)d_in[15];
    const float* bw_b2  = (const float*)d_in[16];
    float* out = (float*)d_out;

    uint32_t *p_qkh, *p_vth;
    float *p_h1, *p_h2, *p_ffh, *p_y, *p_xa, *p_po, *p_l, *p_part;
    cudaGetSymbolAddress((void**)&p_qkh,  g_qkh);
    cudaGetSymbolAddress((void**)&p_vth,  g_vth);
    cudaGetSymbolAddress((void**)&p_h1,   g_h1);
    cudaGetSymbolAddress((void**)&p_h2,   g_h2);
    cudaGetSymbolAddress((void**)&p_ffh,  g_ffh);
    cudaGetSymbolAddress((void**)&p_y,    g_y);
    cudaGetSymbolAddress((void**)&p_xa,   g_xa);
    cudaGetSymbolAddress((void**)&p_po,   g_po);
    cudaGetSymbolAddress((void**)&p_l,    g_l);
    cudaGetSymbolAddress((void**)&p_part, g_part);

    cudaFuncSetAttribute(flash_tc_kernel,
                         cudaFuncAttributeMaxDynamicSharedMemorySize, SMEM_FLASH);

    // attention block (vpack + qk projection merged)
    prep_kernel<<<192, 256>>>(x_fea, p_vth, rg_fea, qp_w, qp_b, p_qkh);
    flash_tc_kernel<<<dim3(NPTS/FQB, FSPLIT), 256, SMEM_FLASH>>>(
        (const __nv_bfloat16*)p_qkh, p_vth, p_po, p_l);
    ff1_fused_kernel<<<dim3(NPTS/64,4), 256>>>(p_po, p_l, x_fea, ln_g, ln_b,
                                               ff_w1, ff_b1, p_h1, p_ffh);
    ff2ln_tc_kernel<<<NPTS/32, 256>>>(p_ffh, ff_w2, ff_b2, p_h1, ln_g, ln_b, p_h2);

    // meanshift iterations
    for (int it = 0; it < 2; it++) {
        gemm_tc_kernel<64,false,true><<<dim3(NPTS/64,1), 256>>>(p_h2, bw_w1 + it*64*64,
                                                                bw_b1 + it*64, p_y, p_part);
        const float* src = (it == 0) ? x : p_xa;
        float* dst       = (it == 0) ? p_xa : out;
        meanshift_kernel<<<NPTS/16, 256>>>(src, p_y, p_part,
                                           bn_g + it*64, bn_b + it*64,
                                           bw_w2 + it*64*3, bw_b2 + it*3, dst);
    }
}